// round 1
// baseline (speedup 1.0000x reference)
#include <cuda_runtime.h>

// Problem constants
#define BB 256
#define TT 16384
#define ALPHA_F 0.95f

// LIF chunking
#define LCHUNK 512
#define WARM   1536
#define NCHUNK (TT / LCHUNK)   // 32

// ---------------------------------------------------------------------------
// Kernel 1: causal conv, 3 branches (k = 8, 16, 32), scaled by 1/sqrt(k).
// u[b][j][t] = (1/sqrt(k_j)) * sum_i w_j[i] * x[b][t - (k_j-1) + i], x[<0]=0
// Block: 512 threads, handles one (batch, 2048-wide T tile). Each thread
// computes 4 consecutive t for all 3 channels from an smem tile.
// ---------------------------------------------------------------------------
__global__ __launch_bounds__(512) void conv_kernel(
    const float* __restrict__ x,
    const float* __restrict__ w0,
    const float* __restrict__ w1,
    const float* __restrict__ w2,
    float* __restrict__ u)
{
    __shared__ float xs[2080];      // 31 halo + 2048 tile (+1 pad)

    const int b    = blockIdx.x;    // 0..255
    const int tile = blockIdx.y;    // 0..7
    const int t0   = tile * 2048;
    const float* xb = x + (size_t)b * TT;

    // cooperative tile load with left halo of 31 (zeros before t=0)
    for (int i = threadIdx.x; i < 2080; i += 512) {
        int gi = t0 + i - 31;
        xs[i] = (gi >= 0 && gi < TT) ? xb[gi] : 0.0f;
    }

    // pre-scaled weights in registers
    float W2[32], W1[16], W0[8];
#pragma unroll
    for (int i = 0; i < 32; i++) W2[i] = w2[i] * 0.1767766952966369f;   // 1/sqrt(32)
#pragma unroll
    for (int i = 0; i < 16; i++) W1[i] = w1[i] * 0.25f;                 // 1/sqrt(16)
#pragma unroll
    for (int i = 0; i < 8;  i++) W0[i] = w0[i] * 0.3535533905932738f;   // 1/sqrt(8)

    __syncthreads();

    const int tt0 = threadIdx.x * 4;       // 4 outputs per thread

    // window xs[tt0 .. tt0+35] via 9 float4 LDS (16B lane stride -> conflict-free)
    float xv[36];
#pragma unroll
    for (int q = 0; q < 9; q++) {
        float4 v = *reinterpret_cast<const float4*>(&xs[tt0 + 4 * q]);
        xv[4 * q + 0] = v.x; xv[4 * q + 1] = v.y;
        xv[4 * q + 2] = v.z; xv[4 * q + 3] = v.w;
    }

    float a0[4] = {0.f, 0.f, 0.f, 0.f};
    float a1[4] = {0.f, 0.f, 0.f, 0.f};
    float a2[4] = {0.f, 0.f, 0.f, 0.f};

    // k=32 branch: offset 31-(32-1)=0
#pragma unroll
    for (int kk = 0; kk < 32; kk++)
#pragma unroll
        for (int r = 0; r < 4; r++)
            a2[r] = fmaf(W2[kk], xv[kk + r], a2[r]);
    // k=16 branch: offset 31-15=16
#pragma unroll
    for (int kk = 0; kk < 16; kk++)
#pragma unroll
        for (int r = 0; r < 4; r++)
            a1[r] = fmaf(W1[kk], xv[16 + kk + r], a1[r]);
    // k=8 branch: offset 31-7=24
#pragma unroll
    for (int kk = 0; kk < 8; kk++)
#pragma unroll
        for (int r = 0; r < 4; r++)
            a0[r] = fmaf(W0[kk], xv[24 + kk + r], a0[r]);

    const int t = t0 + tt0;
    float* ub = u + (size_t)b * 3 * TT;
    *reinterpret_cast<float4*>(ub + 0 * TT + t) = make_float4(a0[0], a0[1], a0[2], a0[3]);
    *reinterpret_cast<float4*>(ub + 1 * TT + t) = make_float4(a1[0], a1[1], a1[2], a1[3]);
    *reinterpret_cast<float4*>(ub + 2 * TT + t) = make_float4(a2[0], a2[1], a2[2], a2[3]);
}

// ---------------------------------------------------------------------------
// Kernel 2: LIF + winner-take-all scan, time-chunked with warm-up.
// One thread per (chunk, batch). Warp = one chunk x 32 batches (uniform
// trip count). v starts at 0 at max(0, c*L - WARM); spikes committed only
// for t in [c*L, (c+1)*L). Contraction (alpha=0.95) makes committed spikes
// exactly equal to the sequential scan.
// u reads / s writes are 2x float4 per channel per 8 steps: scattered but
// 32B-sector-aligned -> no DRAM byte inflation.
// ---------------------------------------------------------------------------
__global__ __launch_bounds__(128) void lif_kernel(
    const float* __restrict__ u,
    float* __restrict__ s)
{
    const int g = blockIdx.x * 128 + threadIdx.x;  // 0..8191
    const int c = g >> 8;                          // chunk 0..31
    const int b = g & 255;                         // batch

    const int commit = c * LCHUNK;
    int start = commit - WARM;
    if (start < 0) start = 0;
    const int end = commit + LCHUNK;

    const float* u0p = u + (size_t)b * 3 * TT;
    const float* u1p = u0p + TT;
    const float* u2p = u1p + TT;
    float* s0p = s + (size_t)b * 3 * TT;
    float* s1p = s0p + TT;
    float* s2p = s1p + TT;

    float v0 = 0.f, v1 = 0.f, v2 = 0.f;

    for (int t = start; t < end; t += 8) {
        float4 qa0 = *reinterpret_cast<const float4*>(u0p + t);
        float4 qb0 = *reinterpret_cast<const float4*>(u0p + t + 4);
        float4 qa1 = *reinterpret_cast<const float4*>(u1p + t);
        float4 qb1 = *reinterpret_cast<const float4*>(u1p + t + 4);
        float4 qa2 = *reinterpret_cast<const float4*>(u2p + t);
        float4 qb2 = *reinterpret_cast<const float4*>(u2p + t + 4);

        float uu0[8] = {qa0.x, qa0.y, qa0.z, qa0.w, qb0.x, qb0.y, qb0.z, qb0.w};
        float uu1[8] = {qa1.x, qa1.y, qa1.z, qa1.w, qb1.x, qb1.y, qb1.z, qb1.w};
        float uu2[8] = {qa2.x, qa2.y, qa2.z, qa2.w, qb2.x, qb2.y, qb2.z, qb2.w};

        float z0[8], z1[8], z2[8];

#pragma unroll
        for (int r = 0; r < 8; r++) {
            v0 = fmaf(ALPHA_F, v0, uu0[r]);
            v1 = fmaf(ALPHA_F, v1, uu1[r]);
            v2 = fmaf(ALPHA_F, v2, uu2[r]);
            // winner (argmax, first index wins ties) + threshold (v >= 1)
            const bool g01 = (v0 >= v1);
            const bool g02 = (v0 >= v2);
            const bool g12 = (v1 >= v2);
            const bool f0 = g01 && g02 && (v0 >= 1.0f);
            const bool f1 = (!g01) && g12 && (v1 >= 1.0f);
            const bool f2 = (!g02) && (!g12) && (v2 >= 1.0f);
            const float a = f0 ? 1.0f : 0.0f;
            const float bb2 = f1 ? 1.0f : 0.0f;
            const float cc = f2 ? 1.0f : 0.0f;
            v0 -= a;       // THETA = 1
            v1 -= bb2;
            v2 -= cc;
            z0[r] = a; z1[r] = bb2; z2[r] = cc;
        }

        if (t >= commit) {     // uniform across warp (same c)
            *reinterpret_cast<float4*>(s0p + t)     = make_float4(z0[0], z0[1], z0[2], z0[3]);
            *reinterpret_cast<float4*>(s0p + t + 4) = make_float4(z0[4], z0[5], z0[6], z0[7]);
            *reinterpret_cast<float4*>(s1p + t)     = make_float4(z1[0], z1[1], z1[2], z1[3]);
            *reinterpret_cast<float4*>(s1p + t + 4) = make_float4(z1[4], z1[5], z1[6], z1[7]);
            *reinterpret_cast<float4*>(s2p + t)     = make_float4(z2[0], z2[1], z2[2], z2[3]);
            *reinterpret_cast<float4*>(s2p + t + 4) = make_float4(z2[4], z2[5], z2[6], z2[7]);
        }
    }
}

// ---------------------------------------------------------------------------
// Launch. Inputs (metadata order): x [256*16384], w0 [8], w1 [16], w2 [32],
// y [256*16384] (unused by the forward outputs).
// Output: concat(u, s_all), both [256, 3, 16384] float32.
// ---------------------------------------------------------------------------
extern "C" void kernel_launch(void* const* d_in, const int* in_sizes, int n_in,
                              void* d_out, int out_size)
{
    const float* x  = (const float*)d_in[0];
    const float* w0 = (const float*)d_in[1];
    const float* w1 = (const float*)d_in[2];
    const float* w2 = (const float*)d_in[3];

    float* u = (float*)d_out;
    float* s = u + (size_t)BB * 3 * TT;

    dim3 cgrid(BB, TT / 2048);
    conv_kernel<<<cgrid, 512>>>(x, w0, w1, w2, u);

    lif_kernel<<<(NCHUNK * BB) / 128, 128>>>(u, s);
}

// round 2
// speedup vs baseline: 1.9040x; 1.9040x over previous
#include <cuda_runtime.h>

// Problem constants
#define BB 256
#define TT 16384
#define ALPHA_F 0.95f

// LIF chunking: 64 chunks of 256, warm-up 768 steps (contraction 0.95^768 ~ 8e-18)
#define LCHUNK 256
#define WARM   768
#define NCHUNK (TT / LCHUNK)   // 64

// ---------------------------------------------------------------------------
// Kernel 1: causal conv, 3 branches (k = 8, 16, 32), scaled by 1/sqrt(k).
// ---------------------------------------------------------------------------
__global__ __launch_bounds__(512) void conv_kernel(
    const float* __restrict__ x,
    const float* __restrict__ w0,
    const float* __restrict__ w1,
    const float* __restrict__ w2,
    float* __restrict__ u)
{
    __shared__ float xs[2080];      // 31 halo + 2048 tile (+1 pad)

    const int b    = blockIdx.x;    // 0..255
    const int tile = blockIdx.y;    // 0..7
    const int t0   = tile * 2048;
    const float* xb = x + (size_t)b * TT;

    for (int i = threadIdx.x; i < 2080; i += 512) {
        int gi = t0 + i - 31;
        xs[i] = (gi >= 0 && gi < TT) ? xb[gi] : 0.0f;
    }

    float W2[32], W1[16], W0[8];
#pragma unroll
    for (int i = 0; i < 32; i++) W2[i] = w2[i] * 0.1767766952966369f;   // 1/sqrt(32)
#pragma unroll
    for (int i = 0; i < 16; i++) W1[i] = w1[i] * 0.25f;                 // 1/sqrt(16)
#pragma unroll
    for (int i = 0; i < 8;  i++) W0[i] = w0[i] * 0.3535533905932738f;   // 1/sqrt(8)

    __syncthreads();

    const int tt0 = threadIdx.x * 4;

    float xv[36];
#pragma unroll
    for (int q = 0; q < 9; q++) {
        float4 v = *reinterpret_cast<const float4*>(&xs[tt0 + 4 * q]);
        xv[4 * q + 0] = v.x; xv[4 * q + 1] = v.y;
        xv[4 * q + 2] = v.z; xv[4 * q + 3] = v.w;
    }

    float a0[4] = {0.f, 0.f, 0.f, 0.f};
    float a1[4] = {0.f, 0.f, 0.f, 0.f};
    float a2[4] = {0.f, 0.f, 0.f, 0.f};

#pragma unroll
    for (int kk = 0; kk < 32; kk++)
#pragma unroll
        for (int r = 0; r < 4; r++)
            a2[r] = fmaf(W2[kk], xv[kk + r], a2[r]);
#pragma unroll
    for (int kk = 0; kk < 16; kk++)
#pragma unroll
        for (int r = 0; r < 4; r++)
            a1[r] = fmaf(W1[kk], xv[16 + kk + r], a1[r]);
#pragma unroll
    for (int kk = 0; kk < 8; kk++)
#pragma unroll
        for (int r = 0; r < 4; r++)
            a0[r] = fmaf(W0[kk], xv[24 + kk + r], a0[r]);

    const int t = t0 + tt0;
    float* ub = u + (size_t)b * 3 * TT;
    *reinterpret_cast<float4*>(ub + 0 * TT + t) = make_float4(a0[0], a0[1], a0[2], a0[3]);
    *reinterpret_cast<float4*>(ub + 1 * TT + t) = make_float4(a1[0], a1[1], a1[2], a1[3]);
    *reinterpret_cast<float4*>(ub + 2 * TT + t) = make_float4(a2[0], a2[1], a2[2], a2[3]);
}

// ---------------------------------------------------------------------------
// Kernel 2: LIF + WTA scan, time-chunked with warm-up, register double-buffer
// prefetch, short predicate chain. One thread per (chunk, batch).
// chunk id is uniform per 128-thread block (256 batches per chunk).
// ---------------------------------------------------------------------------
__global__ __launch_bounds__(128) void lif_kernel(
    const float* __restrict__ u,
    float* __restrict__ s)
{
    const int g = blockIdx.x * 128 + threadIdx.x;  // 0..16383
    const int c = g >> 8;                          // chunk 0..63
    const int b = g & 255;                         // batch

    const int commit = c * LCHUNK;
    int start = commit - WARM;
    if (start < 0) start = 0;
    const int end = commit + LCHUNK;

    const float* u0p = u + (size_t)b * 3 * TT;
    const float* u1p = u0p + TT;
    const float* u2p = u1p + TT;
    float* s0p = s + (size_t)b * 3 * TT;
    float* s1p = s0p + TT;
    float* s2p = s1p + TT;

    float y0 = 0.f, y1 = 0.f, y2 = 0.f;   // post-subtract membrane state

    // prefetch buffers: 6 float4 per 8-step group
    float4 n0a = *reinterpret_cast<const float4*>(u0p + start);
    float4 n0b = *reinterpret_cast<const float4*>(u0p + start + 4);
    float4 n1a = *reinterpret_cast<const float4*>(u1p + start);
    float4 n1b = *reinterpret_cast<const float4*>(u1p + start + 4);
    float4 n2a = *reinterpret_cast<const float4*>(u2p + start);
    float4 n2b = *reinterpret_cast<const float4*>(u2p + start + 4);

    for (int t = start; t < end; t += 8) {
        // consume current, prefetch next group
        float4 qa0 = n0a, qb0 = n0b, qa1 = n1a, qb1 = n1b, qa2 = n2a, qb2 = n2b;
        const int tn = t + 8;
        if (tn < end) {
            n0a = *reinterpret_cast<const float4*>(u0p + tn);
            n0b = *reinterpret_cast<const float4*>(u0p + tn + 4);
            n1a = *reinterpret_cast<const float4*>(u1p + tn);
            n1b = *reinterpret_cast<const float4*>(u1p + tn + 4);
            n2a = *reinterpret_cast<const float4*>(u2p + tn);
            n2b = *reinterpret_cast<const float4*>(u2p + tn + 4);
        }

        const float uu0[8] = {qa0.x, qa0.y, qa0.z, qa0.w, qb0.x, qb0.y, qb0.z, qb0.w};
        const float uu1[8] = {qa1.x, qa1.y, qa1.z, qa1.w, qb1.x, qb1.y, qb1.z, qb1.w};
        const float uu2[8] = {qa2.x, qa2.y, qa2.z, qa2.w, qb2.x, qb2.y, qb2.z, qb2.w};

        float z0[8], z1[8], z2[8];

#pragma unroll
        for (int r = 0; r < 8; r++) {
            // w = alpha*y + u  (matches reference mul+add up to fma rounding;
            // contraction keeps spikes exact)
            const float w0 = fmaf(ALPHA_F, y0, uu0[r]);
            const float w1 = fmaf(ALPHA_F, y1, uu1[r]);
            const float w2 = fmaf(ALPHA_F, y2, uu2[r]);
            // WTA (argmax, first-index wins ties) + threshold (w >= 1)
            const bool g01 = (w0 >= w1);
            const bool g02 = (w0 >= w2);
            const bool g12 = (w1 >= w2);
            const bool f0 = g01 & g02 & (w0 >= 1.0f);
            const bool f1 = (!g01) & g12 & (w1 >= 1.0f);
            const bool f2 = (!g02) & (!g12) & (w2 >= 1.0f);
            const float a  = f0 ? 1.0f : 0.0f;
            const float bb = f1 ? 1.0f : 0.0f;
            const float cc = f2 ? 1.0f : 0.0f;
            y0 = w0 - a;      // exact (theta = 1)
            y1 = w1 - bb;
            y2 = w2 - cc;
            z0[r] = a; z1[r] = bb; z2[r] = cc;
        }

        if (t >= commit) {    // uniform per block
            *reinterpret_cast<float4*>(s0p + t)     = make_float4(z0[0], z0[1], z0[2], z0[3]);
            *reinterpret_cast<float4*>(s0p + t + 4) = make_float4(z0[4], z0[5], z0[6], z0[7]);
            *reinterpret_cast<float4*>(s1p + t)     = make_float4(z1[0], z1[1], z1[2], z1[3]);
            *reinterpret_cast<float4*>(s1p + t + 4) = make_float4(z1[4], z1[5], z1[6], z1[7]);
            *reinterpret_cast<float4*>(s2p + t)     = make_float4(z2[0], z2[1], z2[2], z2[3]);
            *reinterpret_cast<float4*>(s2p + t + 4) = make_float4(z2[4], z2[5], z2[6], z2[7]);
        }
    }
}

// ---------------------------------------------------------------------------
// Launch. Inputs: x [256*16384], w0 [8], w1 [16], w2 [32], y (unused).
// Output: concat(u, s_all), both [256, 3, 16384] float32.
// ---------------------------------------------------------------------------
extern "C" void kernel_launch(void* const* d_in, const int* in_sizes, int n_in,
                              void* d_out, int out_size)
{
    const float* x  = (const float*)d_in[0];
    const float* w0 = (const float*)d_in[1];
    const float* w1 = (const float*)d_in[2];
    const float* w2 = (const float*)d_in[3];

    float* u = (float*)d_out;
    float* s = u + (size_t)BB * 3 * TT;

    dim3 cgrid(BB, TT / 2048);
    conv_kernel<<<cgrid, 512>>>(x, w0, w1, w2, u);

    lif_kernel<<<(NCHUNK * BB) / 128, 128>>>(u, s);
}

// round 3
// speedup vs baseline: 2.6724x; 1.4036x over previous
#include <cuda_runtime.h>

// Problem constants
#define BB   256
#define TTOT 16384
#define ALPHA_F 0.95f

// LIF chunking: 64 chunks of 256, warm-up 512 (0.95^512 ~ 4e-12)
#define LCHUNK 256
#define WARM   512
#define NCHUNK (TTOT / LCHUNK)   // 64

// lif smem tiling
#define TTILE 32
#define BPAD  129                   // padded batch dim (conflict-free)
#define CHSZ  (TTILE * BPAD)        // 4128 floats per channel plane
#define BUFSZ (3 * CHSZ)            // 12384 floats = 49.5 KB
#define LIF_SMEM_BYTES (3 * BUFSZ * 4)   // 2 u-buffers + 1 s-buffer = 148608 B

// ---------------------------------------------------------------------------
// Kernel 1: causal conv, 3 branches (k = 8, 16, 32), scaled by 1/sqrt(k).
// ---------------------------------------------------------------------------
__global__ __launch_bounds__(512) void conv_kernel(
    const float* __restrict__ x,
    const float* __restrict__ w0,
    const float* __restrict__ w1,
    const float* __restrict__ w2,
    float* __restrict__ u)
{
    __shared__ float xs[2080];      // 31 halo + 2048 tile (+1 pad)

    const int b    = blockIdx.x;    // 0..255
    const int tile = blockIdx.y;    // 0..7
    const int t0   = tile * 2048;
    const float* xb = x + (size_t)b * TTOT;

    for (int i = threadIdx.x; i < 2080; i += 512) {
        int gi = t0 + i - 31;
        xs[i] = (gi >= 0 && gi < TTOT) ? xb[gi] : 0.0f;
    }

    float W2[32], W1[16], W0[8];
#pragma unroll
    for (int i = 0; i < 32; i++) W2[i] = w2[i] * 0.1767766952966369f;   // 1/sqrt(32)
#pragma unroll
    for (int i = 0; i < 16; i++) W1[i] = w1[i] * 0.25f;                 // 1/sqrt(16)
#pragma unroll
    for (int i = 0; i < 8;  i++) W0[i] = w0[i] * 0.3535533905932738f;   // 1/sqrt(8)

    __syncthreads();

    const int tt0 = threadIdx.x * 4;

    float xv[36];
#pragma unroll
    for (int q = 0; q < 9; q++) {
        float4 v = *reinterpret_cast<const float4*>(&xs[tt0 + 4 * q]);
        xv[4 * q + 0] = v.x; xv[4 * q + 1] = v.y;
        xv[4 * q + 2] = v.z; xv[4 * q + 3] = v.w;
    }

    float a0[4] = {0.f, 0.f, 0.f, 0.f};
    float a1[4] = {0.f, 0.f, 0.f, 0.f};
    float a2[4] = {0.f, 0.f, 0.f, 0.f};

#pragma unroll
    for (int kk = 0; kk < 32; kk++)
#pragma unroll
        for (int r = 0; r < 4; r++)
            a2[r] = fmaf(W2[kk], xv[kk + r], a2[r]);
#pragma unroll
    for (int kk = 0; kk < 16; kk++)
#pragma unroll
        for (int r = 0; r < 4; r++)
            a1[r] = fmaf(W1[kk], xv[16 + kk + r], a1[r]);
#pragma unroll
    for (int kk = 0; kk < 8; kk++)
#pragma unroll
        for (int r = 0; r < 4; r++)
            a0[r] = fmaf(W0[kk], xv[24 + kk + r], a0[r]);

    const int t = t0 + tt0;
    float* ub = u + (size_t)b * 3 * TTOT;
    *reinterpret_cast<float4*>(ub + 0 * TTOT + t) = make_float4(a0[0], a0[1], a0[2], a0[3]);
    *reinterpret_cast<float4*>(ub + 1 * TTOT + t) = make_float4(a1[0], a1[1], a1[2], a1[3]);
    *reinterpret_cast<float4*>(ub + 2 * TTOT + t) = make_float4(a2[0], a2[1], a2[2], a2[3]);
}

// ---------------------------------------------------------------------------
// Kernel 2: LIF + WTA scan, smem-staged.
// Block = 128 threads = one chunk x 128 batches (2 blocks per chunk).
// u tiles [3][32][128b] staged coalesced into smem (layout [ch][t][BPAD]),
// scan reads conflict-free scalar LDS; spikes staged back out coalesced.
// ---------------------------------------------------------------------------
__global__ __launch_bounds__(128) void lif_kernel(
    const float* __restrict__ u,
    float* __restrict__ s)
{
    extern __shared__ float sm[];
    float* buf0 = sm;
    float* buf1 = sm + BUFSZ;
    float* sbuf = sm + 2 * BUFSZ;

    const int tid   = threadIdx.x;
    const int c     = (int)blockIdx.x >> 1;
    const int bbase = ((int)blockIdx.x & 1) << 7;

    const int commit = c * LCHUNK;
    int start = commit - WARM; if (start < 0) start = 0;
    const int end    = commit + LCHUNK;
    const int ntiles = (end - start) >> 5;

    // chunk map (3072 16B-chunks / tile, 24 per thread, 2 batches of 12):
    // idx = (h*12 + j)*128 + tid ; row = idx>>3 ; o = idx&7
    // ch = row>>7 ; br = row&127 ; global row = u[(bbase+br)*3 + ch][t0 + 4o]
#define LD_BATCH(t0v, h, pf)                                                   \
    {                                                                          \
        _Pragma("unroll")                                                      \
        for (int j = 0; j < 12; j++) {                                         \
            int idx = ((h) * 12 + j) * 128 + tid;                              \
            int row = idx >> 3;                                                \
            int o   = idx & 7;                                                 \
            int ch  = row >> 7;                                                \
            int br  = row & 127;                                               \
            const float* g = u + ((size_t)((bbase + br) * 3 + ch)) * TTOT      \
                               + (t0v) + 4 * o;                                \
            pf[j] = *reinterpret_cast<const float4*>(g);                       \
        }                                                                      \
    }
#define ST_BATCH(dst, h, pf)                                                   \
    {                                                                          \
        _Pragma("unroll")                                                      \
        for (int j = 0; j < 12; j++) {                                         \
            int idx = ((h) * 12 + j) * 128 + tid;                              \
            int row = idx >> 3;                                                \
            int o   = idx & 7;                                                 \
            int ch  = row >> 7;                                                \
            int br  = row & 127;                                               \
            float* p = (dst) + ch * CHSZ + (4 * o) * BPAD + br;                \
            p[0 * BPAD] = pf[j].x;                                             \
            p[1 * BPAD] = pf[j].y;                                             \
            p[2 * BPAD] = pf[j].z;                                             \
            p[3 * BPAD] = pf[j].w;                                             \
        }                                                                      \
    }

    // prime tile 0 into buf0
    {
        float4 pa[12], pb[12];
        LD_BATCH(start, 0, pa);
        LD_BATCH(start, 1, pb);
        ST_BATCH(buf0, 0, pa);
        ST_BATCH(buf0, 1, pb);
    }
    __syncthreads();

    float y0 = 0.f, y1 = 0.f, y2 = 0.f;

    for (int i = 0; i < ntiles; i++) {
        const int t0 = start + i * TTILE;
        const float* Bc = (i & 1) ? buf1 : buf0;
        float*       Bn = (i & 1) ? buf0 : buf1;
        const bool has_next  = (i + 1 < ntiles);
        const bool is_commit = (t0 >= commit);

        float4 pf[12];
        if (has_next) LD_BATCH(t0 + TTILE, 0, pf);

#pragma unroll
        for (int t = 0; t < 16; t++) {
            const float u0 = Bc[0 * CHSZ + t * BPAD + tid];
            const float u1 = Bc[1 * CHSZ + t * BPAD + tid];
            const float u2 = Bc[2 * CHSZ + t * BPAD + tid];
            const float w0 = fmaf(ALPHA_F, y0, u0);
            const float w1 = fmaf(ALPHA_F, y1, u1);
            const float w2 = fmaf(ALPHA_F, y2, u2);
            const bool g01 = (w0 >= w1), g02 = (w0 >= w2), g12 = (w1 >= w2);
            const bool f0 = g01 & g02 & (w0 >= 1.0f);
            const bool f1 = (!g01) & g12 & (w1 >= 1.0f);
            const bool f2 = (!g02) & (!g12) & (w2 >= 1.0f);
            const float a  = f0 ? 1.0f : 0.0f;
            const float bb = f1 ? 1.0f : 0.0f;
            const float cc = f2 ? 1.0f : 0.0f;
            y0 = w0 - a; y1 = w1 - bb; y2 = w2 - cc;
            if (is_commit) {
                sbuf[0 * CHSZ + t * BPAD + tid] = a;
                sbuf[1 * CHSZ + t * BPAD + tid] = bb;
                sbuf[2 * CHSZ + t * BPAD + tid] = cc;
            }
        }

        if (has_next) {
            ST_BATCH(Bn, 0, pf);          // LDG issued ~16 steps ago: covered
            LD_BATCH(t0 + TTILE, 1, pf);
        }

#pragma unroll
        for (int t = 16; t < 32; t++) {
            const float u0 = Bc[0 * CHSZ + t * BPAD + tid];
            const float u1 = Bc[1 * CHSZ + t * BPAD + tid];
            const float u2 = Bc[2 * CHSZ + t * BPAD + tid];
            const float w0 = fmaf(ALPHA_F, y0, u0);
            const float w1 = fmaf(ALPHA_F, y1, u1);
            const float w2 = fmaf(ALPHA_F, y2, u2);
            const bool g01 = (w0 >= w1), g02 = (w0 >= w2), g12 = (w1 >= w2);
            const bool f0 = g01 & g02 & (w0 >= 1.0f);
            const bool f1 = (!g01) & g12 & (w1 >= 1.0f);
            const bool f2 = (!g02) & (!g12) & (w2 >= 1.0f);
            const float a  = f0 ? 1.0f : 0.0f;
            const float bb = f1 ? 1.0f : 0.0f;
            const float cc = f2 ? 1.0f : 0.0f;
            y0 = w0 - a; y1 = w1 - bb; y2 = w2 - cc;
            if (is_commit) {
                sbuf[0 * CHSZ + t * BPAD + tid] = a;
                sbuf[1 * CHSZ + t * BPAD + tid] = bb;
                sbuf[2 * CHSZ + t * BPAD + tid] = cc;
            }
        }

        if (has_next) ST_BATCH(Bn, 1, pf);
        __syncthreads();   // staging of Bn complete; all reads of Bc + sbuf writes done

        if (is_commit) {
            // coalesced spike writeback: same chunk map as staging
#pragma unroll
            for (int q = 0; q < 24; q++) {
                int idx = q * 128 + tid;
                int row = idx >> 3;
                int o   = idx & 7;
                int ch  = row >> 7;
                int br  = row & 127;
                const float* p = sbuf + ch * CHSZ + (4 * o) * BPAD + br;
                float4 v = make_float4(p[0], p[BPAD], p[2 * BPAD], p[3 * BPAD]);
                float* g = s + ((size_t)((bbase + br) * 3 + ch)) * TTOT + t0 + 4 * o;
                *reinterpret_cast<float4*>(g) = v;
            }
            __syncthreads();   // sbuf drained before next commit tile refills it
        }
    }
#undef LD_BATCH
#undef ST_BATCH
}

// ---------------------------------------------------------------------------
// Launch. Inputs: x [256*16384], w0 [8], w1 [16], w2 [32], y (unused).
// Output: concat(u, s_all), both [256, 3, 16384] float32.
// ---------------------------------------------------------------------------
extern "C" void kernel_launch(void* const* d_in, const int* in_sizes, int n_in,
                              void* d_out, int out_size)
{
    const float* x  = (const float*)d_in[0];
    const float* w0 = (const float*)d_in[1];
    const float* w1 = (const float*)d_in[2];
    const float* w2 = (const float*)d_in[3];

    float* u = (float*)d_out;
    float* s = u + (size_t)BB * 3 * TTOT;

    cudaFuncSetAttribute(lif_kernel, cudaFuncAttributeMaxDynamicSharedMemorySize,
                         LIF_SMEM_BYTES);

    dim3 cgrid(BB, TTOT / 2048);
    conv_kernel<<<cgrid, 512>>>(x, w0, w1, w2, u);

    lif_kernel<<<NCHUNK * 2, 128, LIF_SMEM_BYTES>>>(u, s);
}